// round 2
// baseline (speedup 1.0000x reference)
#include <cuda_runtime.h>
#include <cuda_bf16.h>

typedef unsigned long long u64;

// Problem constants
#define Bc   64
#define DINc 150528
#define Dc   512
#define Cc   100
#define Mc   64
#define NFc  256
#define KC   1024
#define NCH  147          // 147 * 1024 = 150528
#define DT   128

// Scratch (static device memory — no allocation)
__device__ float g_partial[NCH * Bc * Dc];   // split-K partials: [chunk][b][d]
__device__ float g_f[Bc * Dc];               // normalized features
__device__ float g_kwp[2 * Cc * NFc];        // kw partial per m-half

// ---------------------------------------------------------------------------
// packed f32x2 helpers (sm_100+ PTX)
// ---------------------------------------------------------------------------
__device__ __forceinline__ u64 splat2(float x) {
    u64 r;
    asm("mov.b64 %0, {%1, %1};" : "=l"(r) : "f"(x));
    return r;
}
__device__ __forceinline__ void fma2(u64& d, u64 a, u64 b) {
    asm("fma.rn.f32x2 %0, %1, %2, %0;" : "+l"(d) : "l"(a), "l"(b));
}
__device__ __forceinline__ float2 unpack2(u64 v) {
    float2 r;
    asm("mov.b64 {%0, %1}, %2;" : "=f"(r.x), "=f"(r.y) : "l"(v));
    return r;
}

// ---------------------------------------------------------------------------
// K1: split-K GEMM  f_raw = image @ W_enc  (64 x 150528) * (150528 x 512)
// grid (4 d-tiles, 147 k-chunks), 256 threads.
// Each block: 64 x 128 output tile over a 1024-deep K chunk -> g_partial.
// Inner loop uses fma.rn.f32x2 (2 FMAs/inst) to double fp32 throughput.
// ---------------------------------------------------------------------------
__global__ void __launch_bounds__(256)
gemm_kernel(const float* __restrict__ A, const float* __restrict__ W) {
    __shared__ float As[32 * 68];    // [kk][b] (padded stride 68)
    __shared__ float Bs[32 * 128];   // [kk][d]

    const int t  = threadIdx.x;
    const int tx = t & 31;           // column group (4 cols)
    const int ty = t >> 5;           // row group (8 rows)
    const int dt0 = blockIdx.x * DT;
    const size_t kb = (size_t)blockIdx.y * KC;

    u64 acc[4][4];                   // [row-pair][col], each holds rows (2i, 2i+1)
#pragma unroll
    for (int i = 0; i < 4; i++)
#pragma unroll
        for (int j = 0; j < 4; j++) acc[i][j] = 0ull;

    for (int k0 = 0; k0 < KC; k0 += 32) {
        // Load A tile: 64 rows x 32 k  (512 float4, 2 per thread), transpose to As[kk][b]
#pragma unroll
        for (int v = 0; v < 2; v++) {
            int ss = t * 2 + v;
            int b  = ss >> 3;
            int f4 = ss & 7;
            float4 av = *(const float4*)&A[(size_t)b * DINc + kb + k0 + f4 * 4];
            As[(f4 * 4 + 0) * 68 + b] = av.x;
            As[(f4 * 4 + 1) * 68 + b] = av.y;
            As[(f4 * 4 + 2) * 68 + b] = av.z;
            As[(f4 * 4 + 3) * 68 + b] = av.w;
        }
        // Load B tile: 32 k x 128 d (1024 float4, 4 per thread), coalesced
#pragma unroll
        for (int i = 0; i < 4; i++) {
            int ss = t + i * 256;
            int kk = ss >> 5;
            int dv = ss & 31;
            *(float4*)&Bs[kk * 128 + dv * 4] =
                *(const float4*)&W[(kb + k0 + kk) * (size_t)Dc + dt0 + dv * 4];
        }
        __syncthreads();

#pragma unroll
        for (int kk = 0; kk < 32; kk++) {
            u64 pa[4];
#pragma unroll
            for (int i = 0; i < 4; i++)
                pa[i] = *(const u64*)&As[kk * 68 + ty * 8 + 2 * i];  // row pair (packed)
            float4 b4 = *(const float4*)&Bs[kk * 128 + tx * 4];
            u64 pb0 = splat2(b4.x), pb1 = splat2(b4.y);
            u64 pb2 = splat2(b4.z), pb3 = splat2(b4.w);
#pragma unroll
            for (int i = 0; i < 4; i++) {
                fma2(acc[i][0], pa[i], pb0);
                fma2(acc[i][1], pa[i], pb1);
                fma2(acc[i][2], pa[i], pb2);
                fma2(acc[i][3], pa[i], pb3);
            }
        }
        __syncthreads();
    }

    // Store partials, coalesced float4 per row
#pragma unroll
    for (int i = 0; i < 4; i++) {
        float2 c0 = unpack2(acc[i][0]);
        float2 c1 = unpack2(acc[i][1]);
        float2 c2 = unpack2(acc[i][2]);
        float2 c3 = unpack2(acc[i][3]);
        int row = ty * 8 + i * 2;
        size_t base = ((size_t)(blockIdx.y * 64 + row)) * Dc + dt0 + tx * 4;
        float4 v0 = make_float4(c0.x, c1.x, c2.x, c3.x);
        float4 v1 = make_float4(c0.y, c1.y, c2.y, c3.y);
        *(float4*)&g_partial[base]       = v0;
        *(float4*)&g_partial[base + Dc]  = v1;
    }
}

// ---------------------------------------------------------------------------
// K2: reduce split-K partials + L2-normalize rows.  grid(64), 256 threads.
// ---------------------------------------------------------------------------
__global__ void __launch_bounds__(256)
reduce_norm_kernel() {
    const int b = blockIdx.x;
    const int t = threadIdx.x;
    float v0 = 0.f, v1 = 0.f;
#pragma unroll 7
    for (int ch = 0; ch < NCH; ch++) {
        const float* p = &g_partial[((size_t)ch * Bc + b) * Dc];
        v0 += p[t];
        v1 += p[t + 256];
    }
    __shared__ float red[256];
    red[t] = v0 * v0 + v1 * v1;
    __syncthreads();
    for (int s = 128; s > 0; s >>= 1) {
        if (t < s) red[t] += red[t + s];
        __syncthreads();
    }
    __shared__ float inv;
    if (t == 0) inv = rsqrtf(red[0]);
    __syncthreads();
    g_f[b * Dc + t]       = v0 * inv;
    g_f[b * Dc + t + 256] = v1 * inv;
}

// ---------------------------------------------------------------------------
// K3: per-class key softmax -> w[c,m] -> kw partial.
// grid (100 classes, 2 m-halves), 256 threads. Static smem < 34 KB.
// kw[c,f] = sum_m keys_sel[c,m,f] * w[c,m];  stored per half in g_kwp.
// ---------------------------------------------------------------------------
__global__ void __launch_bounds__(256)
wkw_kernel(const float* __restrict__ text, const float* __restrict__ keys,
           const int* __restrict__ indices, const float* __restrict__ gamma_p) {
    __shared__ float keys_s[32 * 256];   // gathered keys half-tile [ml][f]
    __shared__ float ts[256];            // gathered text row
    __shared__ float wsh[32];
    __shared__ int idx[256];

    const int c  = blockIdx.x;
    const int mh = blockIdx.y;           // m half: 0 or 1
    const int t  = threadIdx.x;

    idx[t] = indices[c * NFc + t];
    __syncthreads();

    // Gather keys_sel half: 32 m-rows x 256 f
    for (int s = t; s < 32 * 256; s += 256) {
        int ml = s >> 8;
        int f  = s & 255;
        keys_s[s] = keys[((size_t)(c * Mc + mh * 32 + ml)) * Dc + idx[f]];
    }
    __syncthreads();

    const int ml = t >> 3;               // 0..31
    const int p  = t & 7;                // 8 lanes per m, 32 f each
    float denom = 0.f, numer = 0.f;

    for (int j = 0; j < Cc; j++) {
        ts[t] = text[j * Dc + idx[t]];
        __syncthreads();
        float s = 0.f;
#pragma unroll 8
        for (int q = 0; q < 32; q++) {
            int fq = p * 32 + ((q + t) & 31);   // lane-rotated -> conflict-free
            s += keys_s[ml * 256 + fq] * ts[fq];
        }
        s += __shfl_xor_sync(0xffffffffu, s, 1);
        s += __shfl_xor_sync(0xffffffffu, s, 2);
        s += __shfl_xor_sync(0xffffffffu, s, 4);
        float e = expf(s);
        denom += e;
        if (j == c) numer = e;
        __syncthreads();
    }

    if (p == 0) {
        float pcc = numer / denom;
        float KL  = log2f((1.f + 1e-6f) / (pcc + 1e-6f));
        wsh[ml]   = expf(KL * gamma_p[0]);
    }
    __syncthreads();

    // kw partial over this m half
    float acc = 0.f;
#pragma unroll 8
    for (int mm = 0; mm < 32; mm++)
        acc += keys_s[mm * 256 + t] * wsh[mm];
    g_kwp[(size_t)mh * Cc * NFc + c * NFc + t] = acc;
}

// ---------------------------------------------------------------------------
// K4: final fused epilogue. grid(100 classes), 256 threads.
// out[b,c] = alpha*exp(beta*cache-beta) + exp(ls)*(f[b]·text[c])
// cache = (1/M) * sum_f f[b, idx[c,f]] * kw[c,f]
// ---------------------------------------------------------------------------
__global__ void __launch_bounds__(256)
final_kernel(const float* __restrict__ text, const int* __restrict__ indices,
             const float* __restrict__ ls_p, const float* __restrict__ alpha_p,
             const float* __restrict__ beta_p, float* __restrict__ out) {
    __shared__ float tc[512];
    __shared__ float kws[256];
    __shared__ int idx[256];

    const int c = blockIdx.x;
    const int t = threadIdx.x;

    tc[t]       = text[c * Dc + t];
    tc[t + 256] = text[c * Dc + 256 + t];
    idx[t]      = indices[c * NFc + t];
    kws[t]      = g_kwp[c * NFc + t] + g_kwp[Cc * NFc + c * NFc + t];
    __syncthreads();

    const int b = t >> 2;                // 0..63
    const int p = t & 3;                 // 4 lanes per b
    const float* fb = &g_f[b * Dc];

    float clip = 0.f;
#pragma unroll 8
    for (int q = 0; q < 32; q++) {
        float4 fv = *(const float4*)&fb[p * 128 + q * 4];
        float4 tv = *(const float4*)&tc[p * 128 + q * 4];
        clip += fv.x * tv.x + fv.y * tv.y + fv.z * tv.z + fv.w * tv.w;
    }
    float cache = 0.f;
#pragma unroll 8
    for (int q = 0; q < 64; q++) {
        int ff = p * 64 + q;
        cache += fb[idx[ff]] * kws[ff];
    }
    clip  += __shfl_xor_sync(0xffffffffu, clip, 1);
    clip  += __shfl_xor_sync(0xffffffffu, clip, 2);
    cache += __shfl_xor_sync(0xffffffffu, cache, 1);
    cache += __shfl_xor_sync(0xffffffffu, cache, 2);

    if (p == 0) {
        float cl = cache * (1.f / (float)Mc);
        float cache_logit = expf(beta_p[0] * cl - beta_p[0]);
        out[b * Cc + c] = alpha_p[0] * cache_logit + expf(ls_p[0]) * clip;
    }
}

// ---------------------------------------------------------------------------
// Launch
// ---------------------------------------------------------------------------
extern "C" void kernel_launch(void* const* d_in, const int* in_sizes, int n_in,
                              void* d_out, int out_size) {
    const float* image   = (const float*)d_in[0];
    const float* W_enc   = (const float*)d_in[1];
    const float* text    = (const float*)d_in[2];
    const float* keys    = (const float*)d_in[3];
    const float* ls      = (const float*)d_in[4];
    const int*   indices = (const int*)d_in[5];
    const float* alpha   = (const float*)d_in[6];
    const float* beta    = (const float*)d_in[7];
    const float* gamma   = (const float*)d_in[8];
    float* out = (float*)d_out;

    gemm_kernel<<<dim3(4, NCH), 256>>>(image, W_enc);
    reduce_norm_kernel<<<Bc, 256>>>();
    wkw_kernel<<<dim3(Cc, 2), 256>>>(text, keys, indices, gamma);
    final_kernel<<<Cc, 256>>>(text, indices, ls, alpha, beta, out);
}

// round 4
// speedup vs baseline: 1.3950x; 1.3950x over previous
#include <cuda_runtime.h>
#include <cuda_bf16.h>

typedef unsigned int u32;
typedef unsigned long long u64;

#define Bc   64
#define DINc 150528
#define Dc   512
#define Cc   100
#define Mc   64
#define NFc  256
#define KC   1024
#define NCH  147
#define DT   256

__device__ float g_partial[NCH * Bc * Dc];   // split-K partials [chunk][b][d]
__device__ float g_f[Bc * Dc];               // normalized features
__device__ float g_kwp[2 * Cc * NFc];        // kw partials per m-half
__device__ float g_kwd[Cc * Dc];             // dense scattered kw

// ---------------- helpers ----------------
__device__ __forceinline__ u32 smem_u32(const void* p) {
    u32 a;
    asm("{ .reg .u64 t; cvta.to.shared.u64 t, %1; cvt.u32.u64 %0, t; }" : "=r"(a) : "l"(p));
    return a;
}
// split fp32 pair -> packed bf16 hi (x0 in low half) + packed bf16 lo residual
__device__ __forceinline__ void cvt_split(float x0, float x1, u32& h, u32& l) {
    asm("cvt.rn.bf16x2.f32 %0, %1, %2;" : "=r"(h) : "f"(x1), "f"(x0));
    float h0 = __int_as_float(h << 16);
    float h1 = __int_as_float(h & 0xFFFF0000u);
    asm("cvt.rn.bf16x2.f32 %0, %1, %2;" : "=r"(l) : "f"(x1 - h1), "f"(x0 - h0));
}
__device__ __forceinline__ void ldmA(u32* r, u32 addr) {
    asm volatile("ldmatrix.sync.aligned.m8n8.x4.shared.b16 {%0,%1,%2,%3}, [%4];"
        : "=r"(r[0]), "=r"(r[1]), "=r"(r[2]), "=r"(r[3]) : "r"(addr));
}
__device__ __forceinline__ void ldmBT(u32* r, u32 addr) {
    asm volatile("ldmatrix.sync.aligned.m8n8.x4.trans.shared.b16 {%0,%1,%2,%3}, [%4];"
        : "=r"(r[0]), "=r"(r[1]), "=r"(r[2]), "=r"(r[3]) : "r"(addr));
}
__device__ __forceinline__ void mma16816(float* c, const u32* a, u32 b0, u32 b1) {
    asm volatile(
        "mma.sync.aligned.m16n8k16.row.col.f32.bf16.bf16.f32 "
        "{%0,%1,%2,%3}, {%4,%5,%6,%7}, {%8,%9}, {%0,%1,%2,%3};"
        : "+f"(c[0]), "+f"(c[1]), "+f"(c[2]), "+f"(c[3])
        : "r"(a[0]), "r"(a[1]), "r"(a[2]), "r"(a[3]), "r"(b0), "r"(b1));
}

// ---------------------------------------------------------------------------
// K1: split-bf16 3-pass HMMA split-K GEMM.  grid(2 d-tiles, 147 k-chunks),
// 256 threads (8 warps, 2x4 layout; warp tile 32m x 64n).
// A smem [m][k2] u32, row stride 20 words (80B).  B smem [k][n2] u32,
// row stride 132 words (528B).  ldmatrix x4 / x4.trans fragment loads.
// ---------------------------------------------------------------------------
__global__ void __launch_bounds__(256, 2)
gemm_mma_kernel(const float* __restrict__ A, const float* __restrict__ W) {
    __shared__ u32 AsH[64 * 20], AsL[64 * 20];
    __shared__ u32 BsH[32 * 132], BsL[32 * 132];

    const int t = threadIdx.x, w = t >> 5, l = t & 31;
    const int wm = w >> 2, wn = w & 3;
    const int dt0 = blockIdx.x * DT;
    const size_t kb = (size_t)blockIdx.y * KC;

    const u32 asH = smem_u32(AsH), asL = smem_u32(AsL);
    const u32 bsH = smem_u32(BsH), bsL = smem_u32(BsL);

    // ldmatrix per-lane address offsets
    const u32 aRowOff = (u32)(wm * 32 + (l & 7) + ((l >> 3) & 1) * 8) * 80
                        + ((l & 16) ? 16u : 0u);
    const u32 bOff = (u32)((l & 7) + ((l >> 3) & 1) * 8) * 528
                     + (u32)(wn * 64 + ((l & 16) ? 8 : 0)) * 2;

    float acc[2][8][4];
#pragma unroll
    for (int i = 0; i < 2; i++)
#pragma unroll
        for (int j = 0; j < 8; j++)
#pragma unroll
            for (int q = 0; q < 4; q++) acc[i][j][q] = 0.f;

    for (int k0 = 0; k0 < KC; k0 += 32) {
        __syncthreads();
        // ---- A tile: 64m x 32k fp32 -> bf16 hi/lo
#pragma unroll
        for (int i = 0; i < 2; i++) {
            int idx = i * 256 + t;
            int m = idx >> 3, kq = idx & 7;
            float4 v = *(const float4*)(A + (size_t)m * DINc + kb + k0 + kq * 4);
            u32 h0, l0, h1, l1;
            cvt_split(v.x, v.y, h0, l0);
            cvt_split(v.z, v.w, h1, l1);
            int woff = m * 20 + kq * 2;
            *(u64*)&AsH[woff] = ((u64)h1 << 32) | h0;
            *(u64*)&AsL[woff] = ((u64)l1 << 32) | l0;
        }
        // ---- B tile: 32k x 256n fp32 -> bf16 hi/lo (row-major [k][n])
#pragma unroll
        for (int i = 0; i < 8; i++) {
            int idx = i * 256 + t;
            int k = idx >> 6, dq = idx & 63;
            float4 v = *(const float4*)(W + (size_t)(kb + k0 + k) * Dc + dt0 + dq * 4);
            u32 h0, l0, h1, l1;
            cvt_split(v.x, v.y, h0, l0);
            cvt_split(v.z, v.w, h1, l1);
            int woff = k * 132 + dq * 2;
            *(u64*)&BsH[woff] = ((u64)h1 << 32) | h0;
            *(u64*)&BsL[woff] = ((u64)l1 << 32) | l0;
        }
        __syncthreads();

#pragma unroll
        for (int pass = 0; pass < 3; pass++) {
            const u32 aB = (pass == 2) ? asL : asH;
            const u32 bB = (pass == 1) ? bsL : bsH;
#pragma unroll
            for (int ks = 0; ks < 2; ks++) {
                u32 a[2][4];
                ldmA(a[0], aB + aRowOff + ks * 32);
                ldmA(a[1], aB + aRowOff + 16 * 80 + ks * 32);
#pragma unroll
                for (int j = 0; j < 4; j++) {
                    u32 b[4];
                    ldmBT(b, bB + bOff + ks * 16 * 528 + j * 32);
                    mma16816(acc[0][2 * j],     a[0], b[0], b[1]);
                    mma16816(acc[0][2 * j + 1], a[0], b[2], b[3]);
                    mma16816(acc[1][2 * j],     a[1], b[0], b[1]);
                    mma16816(acc[1][2 * j + 1], a[1], b[2], b[3]);
                }
            }
        }
    }

    // ---- store partials
    const int g = l >> 2, t4 = l & 3;
#pragma unroll
    for (int mt = 0; mt < 2; mt++)
#pragma unroll
        for (int nt = 0; nt < 8; nt++) {
            int m = wm * 32 + mt * 16 + g;
            int n = dt0 + wn * 64 + nt * 8 + t4 * 2;
            size_t o = ((size_t)(blockIdx.y * 64 + m)) * Dc + n;
            *(float2*)&g_partial[o] =
                make_float2(acc[mt][nt][0], acc[mt][nt][1]);
            *(float2*)&g_partial[o + 8 * (size_t)Dc] =
                make_float2(acc[mt][nt][2], acc[mt][nt][3]);
        }
}

// ---------------------------------------------------------------------------
// K2: reduce split-K partials + L2-normalize rows. grid(64), 256 threads.
// ---------------------------------------------------------------------------
__global__ void __launch_bounds__(256)
reduce_norm_kernel() {
    const int b = blockIdx.x;
    const int t = threadIdx.x;
    float v0 = 0.f, v1 = 0.f;
#pragma unroll 7
    for (int ch = 0; ch < NCH; ch++) {
        const float* p = &g_partial[((size_t)ch * Bc + b) * Dc];
        v0 += p[t];
        v1 += p[t + 256];
    }
    __shared__ float red[256];
    red[t] = v0 * v0 + v1 * v1;
    __syncthreads();
    for (int s = 128; s > 0; s >>= 1) {
        if (t < s) red[t] += red[t + s];
        __syncthreads();
    }
    __shared__ float inv;
    if (t == 0) inv = rsqrtf(red[0]);
    __syncthreads();
    g_f[b * Dc + t]       = v0 * inv;
    g_f[b * Dc + t + 256] = v1 * inv;
}

// ---------------------------------------------------------------------------
// K3: per-class key softmax -> w[c,m] -> kw partial. grid(100,2), 256 thr.
// ---------------------------------------------------------------------------
__global__ void __launch_bounds__(256)
wkw_kernel(const float* __restrict__ text, const float* __restrict__ keys,
           const int* __restrict__ indices, const float* __restrict__ gamma_p) {
    __shared__ float keys_s[32 * 256];
    __shared__ float ts[256];
    __shared__ float wsh[32];
    __shared__ int idx[256];

    const int c  = blockIdx.x;
    const int mh = blockIdx.y;
    const int t  = threadIdx.x;

    idx[t] = indices[c * NFc + t];
    __syncthreads();

    for (int s = t; s < 32 * 256; s += 256) {
        int ml = s >> 8;
        int f  = s & 255;
        keys_s[s] = keys[((size_t)(c * Mc + mh * 32 + ml)) * Dc + idx[f]];
    }
    __syncthreads();

    const int ml = t >> 3;
    const int p  = t & 7;
    float denom = 0.f, numer = 0.f;

    for (int j = 0; j < Cc; j++) {
        ts[t] = text[j * Dc + idx[t]];
        __syncthreads();
        float s = 0.f;
#pragma unroll 8
        for (int q = 0; q < 32; q++) {
            int fq = p * 32 + ((q + t) & 31);
            s += keys_s[ml * 256 + fq] * ts[fq];
        }
        s += __shfl_xor_sync(0xffffffffu, s, 1);
        s += __shfl_xor_sync(0xffffffffu, s, 2);
        s += __shfl_xor_sync(0xffffffffu, s, 4);
        float e = expf(s);
        denom += e;
        if (j == c) numer = e;
        __syncthreads();
    }

    if (p == 0) {
        float pcc = numer / denom;
        float KL  = log2f((1.f + 1e-6f) / (pcc + 1e-6f));
        wsh[ml]   = expf(KL * gamma_p[0]);
    }
    __syncthreads();

    float acc = 0.f;
#pragma unroll 8
    for (int mm = 0; mm < 32; mm++)
        acc += keys_s[mm * 256 + t] * wsh[mm];
    g_kwp[(size_t)mh * Cc * NFc + c * NFc + t] = acc;
}

// ---------------------------------------------------------------------------
// K3b: scatter kw[c,f] into dense kwd[c,d] (accumulating duplicate indices;
// deterministic: each thread owns output d's, scans all f). grid(100), 256.
// ---------------------------------------------------------------------------
__global__ void __launch_bounds__(256)
scatter_kernel(const int* __restrict__ indices) {
    __shared__ float kws[256];
    __shared__ int idx[256];
    const int c = blockIdx.x;
    const int t = threadIdx.x;

    kws[t] = g_kwp[c * NFc + t] + g_kwp[Cc * NFc + c * NFc + t];
    idx[t] = indices[c * NFc + t];
    __syncthreads();

    for (int d = t; d < Dc; d += 256) {
        float s = 0.f;
#pragma unroll 8
        for (int f = 0; f < NFc; f++)
            if (idx[f] == d) s += kws[f];
        g_kwd[c * Dc + d] = s;
    }
}

// ---------------------------------------------------------------------------
// K4: final fused epilogue (dense). grid(100), 256 threads.
// out[b,c] = alpha*exp(beta*cache - beta) + exp(ls)*(f_b . text_c)
// cache = (1/M) * (f_b . kwd_c)
// ---------------------------------------------------------------------------
__global__ void __launch_bounds__(256)
final_kernel(const float* __restrict__ text, const float* __restrict__ ls_p,
             const float* __restrict__ alpha_p, const float* __restrict__ beta_p,
             float* __restrict__ out) {
    __shared__ float tc[512];
    __shared__ float kd[512];

    const int c = blockIdx.x;
    const int t = threadIdx.x;

    tc[t]       = text[c * Dc + t];
    tc[t + 256] = text[c * Dc + 256 + t];
    kd[t]       = g_kwd[c * Dc + t];
    kd[t + 256] = g_kwd[c * Dc + 256 + t];
    __syncthreads();

    const int b = t >> 2;
    const int p = t & 3;
    const float* fb = &g_f[b * Dc];

    float clip = 0.f, cache = 0.f;
#pragma unroll 8
    for (int q = 0; q < 32; q++) {
        float4 fv = *(const float4*)&fb[p * 128 + q * 4];
        float4 tv = *(const float4*)&tc[p * 128 + q * 4];
        float4 kv = *(const float4*)&kd[p * 128 + q * 4];
        clip  += fv.x * tv.x + fv.y * tv.y + fv.z * tv.z + fv.w * tv.w;
        cache += fv.x * kv.x + fv.y * kv.y + fv.z * kv.z + fv.w * kv.w;
    }
    clip  += __shfl_xor_sync(0xffffffffu, clip, 1);
    clip  += __shfl_xor_sync(0xffffffffu, clip, 2);
    cache += __shfl_xor_sync(0xffffffffu, cache, 1);
    cache += __shfl_xor_sync(0xffffffffu, cache, 2);

    if (p == 0) {
        float cl = cache * (1.f / (float)Mc);
        float cache_logit = expf(beta_p[0] * cl - beta_p[0]);
        out[b * Cc + c] = alpha_p[0] * cache_logit + expf(ls_p[0]) * clip;
    }
}

// ---------------------------------------------------------------------------
// Launch
// ---------------------------------------------------------------------------
extern "C" void kernel_launch(void* const* d_in, const int* in_sizes, int n_in,
                              void* d_out, int out_size) {
    const float* image   = (const float*)d_in[0];
    const float* W_enc   = (const float*)d_in[1];
    const float* text    = (const float*)d_in[2];
    const float* keys    = (const float*)d_in[3];
    const float* ls      = (const float*)d_in[4];
    const int*   indices = (const int*)d_in[5];
    const float* alpha   = (const float*)d_in[6];
    const float* beta    = (const float*)d_in[7];
    const float* gamma   = (const float*)d_in[8];
    float* out = (float*)d_out;

    gemm_mma_kernel<<<dim3(2, NCH), 256>>>(image, W_enc);
    reduce_norm_kernel<<<Bc, 256>>>();
    wkw_kernel<<<dim3(Cc, 2), 256>>>(text, keys, indices, gamma);
    scatter_kernel<<<Cc, 256>>>(indices);
    final_kernel<<<Cc, 256>>>(text, ls, alpha, beta, out);
}

// round 5
// speedup vs baseline: 1.6519x; 1.1842x over previous
#include <cuda_runtime.h>
#include <cuda_bf16.h>

typedef unsigned int u32;
typedef unsigned long long u64;

#define Bc   64
#define DINc 150528
#define Dc   512
#define Cc   100
#define Mc   64
#define NFc  256
#define KC   1024
#define NCH  147
#define DT   128

__device__ float g_partial[NCH * Bc * Dc];   // split-K partials [chunk][b][d]
__device__ float g_fraw[Bc * Dc];            // reduced (unnormalized) features
__device__ float g_f[Bc * Dc];               // normalized features
__device__ float g_kwp[2 * Cc * NFc];        // kw partials per m-half
__device__ float g_kwd[Cc * Dc];             // dense scattered kw

// ---------------- helpers ----------------
__device__ __forceinline__ u32 smem_u32(const void* p) {
    u32 a;
    asm("{ .reg .u64 t; cvta.to.shared.u64 t, %1; cvt.u32.u64 %0, t; }" : "=r"(a) : "l"(p));
    return a;
}
// split fp32 pair -> packed bf16 hi (x0 in low half) + packed bf16 lo residual
__device__ __forceinline__ void cvt_split(float x0, float x1, u32& h, u32& l) {
    asm("cvt.rn.bf16x2.f32 %0, %1, %2;" : "=r"(h) : "f"(x1), "f"(x0));
    float h0 = __int_as_float(h << 16);
    float h1 = __int_as_float(h & 0xFFFF0000u);
    asm("cvt.rn.bf16x2.f32 %0, %1, %2;" : "=r"(l) : "f"(x1 - h1), "f"(x0 - h0));
}
__device__ __forceinline__ void ldmA(u32* r, u32 addr) {
    asm volatile("ldmatrix.sync.aligned.m8n8.x4.shared.b16 {%0,%1,%2,%3}, [%4];"
        : "=r"(r[0]), "=r"(r[1]), "=r"(r[2]), "=r"(r[3]) : "r"(addr));
}
__device__ __forceinline__ void ldmBT(u32* r, u32 addr) {
    asm volatile("ldmatrix.sync.aligned.m8n8.x4.trans.shared.b16 {%0,%1,%2,%3}, [%4];"
        : "=r"(r[0]), "=r"(r[1]), "=r"(r[2]), "=r"(r[3]) : "r"(addr));
}
__device__ __forceinline__ void mma16816(float* c, const u32* a, u32 b0, u32 b1) {
    asm volatile(
        "mma.sync.aligned.m16n8k16.row.col.f32.bf16.bf16.f32 "
        "{%0,%1,%2,%3}, {%4,%5,%6,%7}, {%8,%9}, {%0,%1,%2,%3};"
        : "+f"(c[0]), "+f"(c[1]), "+f"(c[2]), "+f"(c[3])
        : "r"(a[0]), "r"(a[1]), "r"(a[2]), "r"(a[3]), "r"(b0), "r"(b1));
}

// ---------------------------------------------------------------------------
// K1: split-bf16 3-pass HMMA split-K GEMM with register double-buffering.
// grid(4 d-tiles, 147 k-chunks), 256 threads (8 warps 2x4; warp tile 32x32).
// A smem [64 m][32 k] bf16, row stride 20 words.  B smem [32 k][128 n] bf16,
// row stride 68 words. Next k-tile's fp32 prefetched into registers so LDG
// latency is covered by the MMA phase.
// ---------------------------------------------------------------------------
__global__ void __launch_bounds__(256, 2)
gemm_mma_kernel(const float* __restrict__ A, const float* __restrict__ W) {
    __shared__ u32 AsH[64 * 20], AsL[64 * 20];
    __shared__ u32 BsH[32 * 68], BsL[32 * 68];

    const int t = threadIdx.x, w = t >> 5, l = t & 31;
    const int wm = w >> 2, wn = w & 3;
    const int dt0 = blockIdx.x * DT;
    const size_t kb = (size_t)blockIdx.y * KC;

    const u32 asH = smem_u32(AsH), asL = smem_u32(AsL);
    const u32 bsH = smem_u32(BsH), bsL = smem_u32(BsL);

    const u32 aRowOff = (u32)(wm * 32 + (l & 7) + ((l >> 3) & 1) * 8) * 80
                        + ((l & 16) ? 16u : 0u);
    const u32 bOff = (u32)((l & 7) + ((l >> 3) & 1) * 8) * 272
                     + (u32)(wn * 32 + ((l & 16) ? 8 : 0)) * 2;

    // per-thread load coordinates
    const int am = t >> 3, akq = t & 7;             // A: 2 tiles of (m, k-quad)
    const int bk = t >> 5, bdq = t & 31;            // B: 4 tiles of (k, d-quad)
    const float* Ap = A + (size_t)am * DINc + kb + akq * 4;
    const float* Wp = W + (size_t)(kb + bk) * Dc + dt0 + bdq * 4;

    float acc[2][4][4];
#pragma unroll
    for (int i = 0; i < 2; i++)
#pragma unroll
        for (int j = 0; j < 4; j++)
#pragma unroll
            for (int q = 0; q < 4; q++) acc[i][j][q] = 0.f;

    float4 pfA[2], pfB[4];
    // initial prefetch (k0 = 0)
#pragma unroll
    for (int i = 0; i < 2; i++) pfA[i] = *(const float4*)(Ap + (size_t)(i * 32) * DINc);
#pragma unroll
    for (int i = 0; i < 4; i++) pfB[i] = *(const float4*)(Wp + (size_t)(i * 8) * Dc);

    for (int k0 = 0; k0 < KC; k0 += 32) {
        // ---- convert current regs -> bf16 hi/lo smem
#pragma unroll
        for (int i = 0; i < 2; i++) {
            u32 h0, l0, h1, l1;
            cvt_split(pfA[i].x, pfA[i].y, h0, l0);
            cvt_split(pfA[i].z, pfA[i].w, h1, l1);
            int woff = (i * 32 + am) * 20 + akq * 2;
            *(u64*)&AsH[woff] = ((u64)h1 << 32) | h0;
            *(u64*)&AsL[woff] = ((u64)l1 << 32) | l0;
        }
#pragma unroll
        for (int i = 0; i < 4; i++) {
            u32 h0, l0, h1, l1;
            cvt_split(pfB[i].x, pfB[i].y, h0, l0);
            cvt_split(pfB[i].z, pfB[i].w, h1, l1);
            int woff = (i * 8 + bk) * 68 + bdq * 2;
            *(u64*)&BsH[woff] = ((u64)h1 << 32) | h0;
            *(u64*)&BsL[woff] = ((u64)l1 << 32) | l0;
        }
        // ---- prefetch next k-tile (completes under the MMA phase)
        if (k0 + 32 < KC) {
#pragma unroll
            for (int i = 0; i < 2; i++)
                pfA[i] = *(const float4*)(Ap + (size_t)(i * 32) * DINc + k0 + 32);
#pragma unroll
            for (int i = 0; i < 4; i++)
                pfB[i] = *(const float4*)(Wp + (size_t)(i * 8 + k0 + 32) * Dc);
        }
        __syncthreads();

#pragma unroll
        for (int pass = 0; pass < 3; pass++) {
            const u32 aB = (pass == 2) ? asL : asH;
            const u32 bB = (pass == 1) ? bsL : bsH;
#pragma unroll
            for (int ks = 0; ks < 2; ks++) {
                u32 a[2][4];
                ldmA(a[0], aB + aRowOff + ks * 32);
                ldmA(a[1], aB + aRowOff + 16 * 80 + ks * 32);
#pragma unroll
                for (int j = 0; j < 2; j++) {
                    u32 b[4];
                    ldmBT(b, bB + bOff + ks * 16 * 272 + j * 32);
                    mma16816(acc[0][2 * j],     a[0], b[0], b[1]);
                    mma16816(acc[0][2 * j + 1], a[0], b[2], b[3]);
                    mma16816(acc[1][2 * j],     a[1], b[0], b[1]);
                    mma16816(acc[1][2 * j + 1], a[1], b[2], b[3]);
                }
            }
        }
        __syncthreads();
    }

    // ---- store partials
    const int g = l >> 2, t4 = l & 3;
#pragma unroll
    for (int mt = 0; mt < 2; mt++)
#pragma unroll
        for (int nt = 0; nt < 4; nt++) {
            int m = wm * 32 + mt * 16 + g;
            int n = dt0 + wn * 32 + nt * 8 + t4 * 2;
            size_t o = ((size_t)(blockIdx.y * 64 + m)) * Dc + n;
            *(float2*)&g_partial[o] =
                make_float2(acc[mt][nt][0], acc[mt][nt][1]);
            *(float2*)&g_partial[o + 8 * (size_t)Dc] =
                make_float2(acc[mt][nt][2], acc[mt][nt][3]);
        }
}

// ---------------------------------------------------------------------------
// K2a: reduce split-K partials. grid(64, 2), 256 threads.
// ---------------------------------------------------------------------------
__global__ void __launch_bounds__(256)
reduce_kernel() {
    const int b = blockIdx.x;
    const int d = blockIdx.y * 256 + threadIdx.x;
    float v = 0.f;
#pragma unroll 7
    for (int ch = 0; ch < NCH; ch++)
        v += g_partial[((size_t)ch * Bc + b) * Dc + d];
    g_fraw[b * Dc + d] = v;
}

// ---------------------------------------------------------------------------
// K2b: L2-normalize rows. grid(64), 256 threads.
// ---------------------------------------------------------------------------
__global__ void __launch_bounds__(256)
norm_kernel() {
    const int b = blockIdx.x;
    const int t = threadIdx.x;
    float v0 = g_fraw[b * Dc + t];
    float v1 = g_fraw[b * Dc + t + 256];
    __shared__ float red[256];
    red[t] = v0 * v0 + v1 * v1;
    __syncthreads();
    for (int s = 128; s > 0; s >>= 1) {
        if (t < s) red[t] += red[t + s];
        __syncthreads();
    }
    __shared__ float inv;
    if (t == 0) inv = rsqrtf(red[0]);
    __syncthreads();
    g_f[b * Dc + t]       = v0 * inv;
    g_f[b * Dc + t + 256] = v1 * inv;
}

// ---------------------------------------------------------------------------
// K3: per-class key softmax -> w[c,m] -> kw partial. grid(100,2), 256 thr.
// Depth-2 register prefetch of the per-j text gather.
// ---------------------------------------------------------------------------
__global__ void __launch_bounds__(256)
wkw_kernel(const float* __restrict__ text, const float* __restrict__ keys,
           const int* __restrict__ indices, const float* __restrict__ gamma_p) {
    __shared__ float keys_s[32 * 256];
    __shared__ float ts[256];
    __shared__ float wsh[32];
    __shared__ int idx[256];

    const int c  = blockIdx.x;
    const int mh = blockIdx.y;
    const int t  = threadIdx.x;

    idx[t] = indices[c * NFc + t];
    __syncthreads();
    const int idxt = idx[t];

    for (int s = t; s < 32 * 256; s += 256) {
        int ml = s >> 8;
        int f  = s & 255;
        keys_s[s] = keys[((size_t)(c * Mc + mh * 32 + ml)) * Dc + idx[f]];
    }

    float tn0 = text[idxt];            // j = 0
    float tn1 = text[Dc + idxt];       // j = 1
    __syncthreads();

    const int ml = t >> 3;
    const int p  = t & 7;
    float denom = 0.f, numer = 0.f;

    for (int j = 0; j < Cc; j++) {
        ts[t] = tn0;
        __syncthreads();
        tn0 = tn1;
        if (j + 2 < Cc) tn1 = text[(j + 2) * Dc + idxt];

        float s = 0.f;
#pragma unroll 8
        for (int q = 0; q < 32; q++) {
            int fq = p * 32 + ((q + t) & 31);
            s += keys_s[ml * 256 + fq] * ts[fq];
        }
        s += __shfl_xor_sync(0xffffffffu, s, 1);
        s += __shfl_xor_sync(0xffffffffu, s, 2);
        s += __shfl_xor_sync(0xffffffffu, s, 4);
        float e = expf(s);
        denom += e;
        if (j == c) numer = e;
        __syncthreads();
    }

    if (p == 0) {
        float pcc = numer / denom;
        float KL  = log2f((1.f + 1e-6f) / (pcc + 1e-6f));
        wsh[ml]   = expf(KL * gamma_p[0]);
    }
    __syncthreads();

    float acc = 0.f;
#pragma unroll 8
    for (int mm = 0; mm < 32; mm++)
        acc += keys_s[mm * 256 + t] * wsh[mm];
    g_kwp[(size_t)mh * Cc * NFc + c * NFc + t] = acc;
}

// ---------------------------------------------------------------------------
// K3b: scatter kw[c,f] into dense kwd[c,d]. grid(100,2), 256 threads.
// Deterministic: each thread owns one d, scans all f.
// ---------------------------------------------------------------------------
__global__ void __launch_bounds__(256)
scatter_kernel(const int* __restrict__ indices) {
    __shared__ float kws[256];
    __shared__ int idx[256];
    const int c = blockIdx.x;
    const int t = threadIdx.x;
    const int d = blockIdx.y * 256 + t;

    kws[t] = g_kwp[c * NFc + t] + g_kwp[Cc * NFc + c * NFc + t];
    idx[t] = indices[c * NFc + t];
    __syncthreads();

    float s = 0.f;
#pragma unroll 16
    for (int f = 0; f < NFc; f++)
        if (idx[f] == d) s += kws[f];
    g_kwd[c * Dc + d] = s;
}

// ---------------------------------------------------------------------------
// K4: final fused epilogue (dense). grid(100), 256 threads.
// ---------------------------------------------------------------------------
__global__ void __launch_bounds__(256)
final_kernel(const float* __restrict__ text, const float* __restrict__ ls_p,
             const float* __restrict__ alpha_p, const float* __restrict__ beta_p,
             float* __restrict__ out) {
    __shared__ float tc[512];
    __shared__ float kd[512];

    const int c = blockIdx.x;
    const int t = threadIdx.x;

    tc[t]       = text[c * Dc + t];
    tc[t + 256] = text[c * Dc + 256 + t];
    kd[t]       = g_kwd[c * Dc + t];
    kd[t + 256] = g_kwd[c * Dc + 256 + t];
    __syncthreads();

    const int b = t >> 2;
    const int p = t & 3;
    const float* fb = &g_f[b * Dc];

    float clip = 0.f, cache = 0.f;
#pragma unroll 8
    for (int q = 0; q < 32; q++) {
        float4 fv = *(const float4*)&fb[p * 128 + q * 4];
        float4 tv = *(const float4*)&tc[p * 128 + q * 4];
        float4 kv = *(const float4*)&kd[p * 128 + q * 4];
        clip  += fv.x * tv.x + fv.y * tv.y + fv.z * tv.z + fv.w * tv.w;
        cache += fv.x * kv.x + fv.y * kv.y + fv.z * kv.z + fv.w * kv.w;
    }
    clip  += __shfl_xor_sync(0xffffffffu, clip, 1);
    clip  += __shfl_xor_sync(0xffffffffu, clip, 2);
    cache += __shfl_xor_sync(0xffffffffu, cache, 1);
    cache += __shfl_xor_sync(0xffffffffu, cache, 2);

    if (p == 0) {
        float cl = cache * (1.f / (float)Mc);
        float cache_logit = expf(beta_p[0] * cl - beta_p[0]);
        out[b * Cc + c] = alpha_p[0] * cache_logit + expf(ls_p[0]) * clip;
    }
}

// ---------------------------------------------------------------------------
// Launch
// ---------------------------------------------------------------------------
extern "C" void kernel_launch(void* const* d_in, const int* in_sizes, int n_in,
                              void* d_out, int out_size) {
    const float* image   = (const float*)d_in[0];
    const float* W_enc   = (const float*)d_in[1];
    const float* text    = (const float*)d_in[2];
    const float* keys    = (const float*)d_in[3];
    const float* ls      = (const float*)d_in[4];
    const int*   indices = (const int*)d_in[5];
    const float* alpha   = (const float*)d_in[6];
    const float* beta    = (const float*)d_in[7];
    const float* gamma   = (const float*)d_in[8];
    float* out = (float*)d_out;

    gemm_mma_kernel<<<dim3(4, NCH), 256>>>(image, W_enc);
    reduce_kernel<<<dim3(Bc, 2), 256>>>();
    norm_kernel<<<Bc, 256>>>();
    wkw_kernel<<<dim3(Cc, 2), 256>>>(text, keys, indices, gamma);
    scatter_kernel<<<dim3(Cc, 2), 256>>>(indices);
    final_kernel<<<Cc, 256>>>(text, ls, alpha, beta, out);
}

// round 6
// speedup vs baseline: 2.1442x; 1.2980x over previous
#include <cuda_runtime.h>
#include <cuda_bf16.h>

typedef unsigned int u32;
typedef unsigned long long u64;

#define Bc   64
#define DINc 150528
#define Dc   512
#define Cc   100
#define Mc   64
#define NFc  256
#define KC   1024
#define NCH  147
#define DT   128
#define JP   112        // padded j extent for S tiles

__device__ float g_partial[NCH * Bc * Dc];   // split-K partials [chunk][b][d]
__device__ float g_fraw[Bc * Dc];
__device__ float g_f[Bc * Dc];
__device__ float g_cnt[Cc * Dc];             // index multiplicity per (c,d)
__device__ float g_spart[Cc * 4 * Mc * JP];  // S partials [c][dchunk][m][j]
__device__ float g_w[Cc * Mc];               // per-key weights
__device__ float g_kwd[Cc * Dc];             // dense kw

// ---------------- helpers ----------------
__device__ __forceinline__ u32 smem_u32(const void* p) {
    u32 a;
    asm("{ .reg .u64 t; cvta.to.shared.u64 t, %1; cvt.u32.u64 %0, t; }" : "=r"(a) : "l"(p));
    return a;
}
__device__ __forceinline__ void cvt_split(float x0, float x1, u32& h, u32& l) {
    asm("cvt.rn.bf16x2.f32 %0, %1, %2;" : "=r"(h) : "f"(x1), "f"(x0));
    float h0 = __int_as_float(h << 16);
    float h1 = __int_as_float(h & 0xFFFF0000u);
    asm("cvt.rn.bf16x2.f32 %0, %1, %2;" : "=r"(l) : "f"(x1 - h1), "f"(x0 - h0));
}
__device__ __forceinline__ void ldmA(u32* r, u32 addr) {
    asm volatile("ldmatrix.sync.aligned.m8n8.x4.shared.b16 {%0,%1,%2,%3}, [%4];"
        : "=r"(r[0]), "=r"(r[1]), "=r"(r[2]), "=r"(r[3]) : "r"(addr));
}
__device__ __forceinline__ void ldmBT(u32* r, u32 addr) {
    asm volatile("ldmatrix.sync.aligned.m8n8.x4.trans.shared.b16 {%0,%1,%2,%3}, [%4];"
        : "=r"(r[0]), "=r"(r[1]), "=r"(r[2]), "=r"(r[3]) : "r"(addr));
}
__device__ __forceinline__ void mma16816(float* c, const u32* a, u32 b0, u32 b1) {
    asm volatile(
        "mma.sync.aligned.m16n8k16.row.col.f32.bf16.bf16.f32 "
        "{%0,%1,%2,%3}, {%4,%5,%6,%7}, {%8,%9}, {%0,%1,%2,%3};"
        : "+f"(c[0]), "+f"(c[1]), "+f"(c[2]), "+f"(c[3])
        : "r"(a[0]), "r"(a[1]), "r"(a[2]), "r"(a[3]), "r"(b0), "r"(b1));
}

// ---------------------------------------------------------------------------
// K1: split-bf16 3-pass HMMA split-K GEMM.  Double-buffered smem -> single
// __syncthreads per k-iter (convert overlaps MMA across warps); fragments
// shared across the 3 passes (16 ldmatrix/iter).  grid(4,147), 256 thr.
// Dynamic smem 55296 B.
// ---------------------------------------------------------------------------
#define A_STRIDE 20
#define B_STRIDE 68
#define A_BUF (64 * A_STRIDE)      // 1280 words
#define B_BUF (32 * B_STRIDE)      // 2176 words
#define GEMM_SMEM ((2 * A_BUF * 2 + 2 * B_BUF * 2) * 4)   // 55296 B

__global__ void __launch_bounds__(256, 2)
gemm_mma_kernel(const float* __restrict__ A, const float* __restrict__ W) {
    extern __shared__ u32 dsm[];
    u32* AsH = dsm;
    u32* AsL = dsm + 2 * A_BUF;
    u32* BsH = dsm + 4 * A_BUF;
    u32* BsL = dsm + 4 * A_BUF + 2 * B_BUF;

    const int t = threadIdx.x, w = t >> 5, l = t & 31;
    const int wm = w >> 2, wn = w & 3;
    const int dt0 = blockIdx.x * DT;
    const size_t kb = (size_t)blockIdx.y * KC;

    const u32 aRowOff = (u32)(wm * 32 + (l & 7) + ((l >> 3) & 1) * 8) * (A_STRIDE * 4)
                        + ((l & 16) ? 16u : 0u);
    const u32 bOff = (u32)((l & 7) + ((l >> 3) & 1) * 8) * (B_STRIDE * 4)
                     + (u32)(wn * 32 + ((l & 16) ? 8 : 0)) * 2;

    const int am = t >> 3, akq = t & 7;
    const int bk = t >> 5, bdq = t & 31;
    const float* Ap = A + (size_t)am * DINc + kb + akq * 4;
    const float* Wp = W + (size_t)(kb + bk) * Dc + dt0 + bdq * 4;

    float acc[2][4][4];
#pragma unroll
    for (int i = 0; i < 2; i++)
#pragma unroll
        for (int j = 0; j < 4; j++)
#pragma unroll
            for (int q = 0; q < 4; q++) acc[i][j][q] = 0.f;

    float4 pfA[2], pfB[4];
#pragma unroll
    for (int i = 0; i < 2; i++) pfA[i] = *(const float4*)(Ap + (size_t)(i * 32) * DINc);
#pragma unroll
    for (int i = 0; i < 4; i++) pfB[i] = *(const float4*)(Wp + (size_t)(i * 8) * Dc);

    for (int k0 = 0; k0 < KC; k0 += 32) {
        const int buf = (k0 >> 5) & 1;
        u32* aH = AsH + buf * A_BUF;
        u32* aL = AsL + buf * A_BUF;
        u32* bH = BsH + buf * B_BUF;
        u32* bL = BsL + buf * B_BUF;

        // convert current regs -> smem
#pragma unroll
        for (int i = 0; i < 2; i++) {
            u32 h0, l0, h1, l1;
            cvt_split(pfA[i].x, pfA[i].y, h0, l0);
            cvt_split(pfA[i].z, pfA[i].w, h1, l1);
            int woff = (i * 32 + am) * A_STRIDE + akq * 2;
            *(u64*)&aH[woff] = ((u64)h1 << 32) | h0;
            *(u64*)&aL[woff] = ((u64)l1 << 32) | l0;
        }
#pragma unroll
        for (int i = 0; i < 4; i++) {
            u32 h0, l0, h1, l1;
            cvt_split(pfB[i].x, pfB[i].y, h0, l0);
            cvt_split(pfB[i].z, pfB[i].w, h1, l1);
            int woff = (i * 8 + bk) * B_STRIDE + bdq * 2;
            *(u64*)&bH[woff] = ((u64)h1 << 32) | h0;
            *(u64*)&bL[woff] = ((u64)l1 << 32) | l0;
        }
        // prefetch next k-tile
        if (k0 + 32 < KC) {
#pragma unroll
            for (int i = 0; i < 2; i++)
                pfA[i] = *(const float4*)(Ap + (size_t)(i * 32) * DINc + k0 + 32);
#pragma unroll
            for (int i = 0; i < 4; i++)
                pfB[i] = *(const float4*)(Wp + (size_t)(i * 8 + k0 + 32) * Dc);
        }
        __syncthreads();

        const u32 aHb = smem_u32(aH), aLb = smem_u32(aL);
        const u32 bHb = smem_u32(bH), bLb = smem_u32(bL);
#pragma unroll
        for (int ks = 0; ks < 2; ks++) {
            u32 fAH[2][4], fAL[2][4];
            ldmA(fAH[0], aHb + aRowOff + ks * 32);
            ldmA(fAH[1], aHb + aRowOff + 16 * (A_STRIDE * 4) + ks * 32);
            ldmA(fAL[0], aLb + aRowOff + ks * 32);
            ldmA(fAL[1], aLb + aRowOff + 16 * (A_STRIDE * 4) + ks * 32);
#pragma unroll
            for (int j = 0; j < 2; j++) {
                u32 fBH[4], fBL[4];
                ldmBT(fBH, bHb + bOff + ks * 16 * (B_STRIDE * 4) + j * 32);
                ldmBT(fBL, bLb + bOff + ks * 16 * (B_STRIDE * 4) + j * 32);
#pragma unroll
                for (int mt = 0; mt < 2; mt++) {
                    mma16816(acc[mt][2 * j],     fAH[mt], fBH[0], fBH[1]);
                    mma16816(acc[mt][2 * j + 1], fAH[mt], fBH[2], fBH[3]);
                    mma16816(acc[mt][2 * j],     fAH[mt], fBL[0], fBL[1]);
                    mma16816(acc[mt][2 * j + 1], fAH[mt], fBL[2], fBL[3]);
                    mma16816(acc[mt][2 * j],     fAL[mt], fBH[0], fBH[1]);
                    mma16816(acc[mt][2 * j + 1], fAL[mt], fBH[2], fBH[3]);
                }
            }
        }
    }

    const int g = l >> 2, t4 = l & 3;
#pragma unroll
    for (int mt = 0; mt < 2; mt++)
#pragma unroll
        for (int nt = 0; nt < 4; nt++) {
            int m = wm * 32 + mt * 16 + g;
            int n = dt0 + wn * 32 + nt * 8 + t4 * 2;
            size_t o = ((size_t)(blockIdx.y * 64 + m)) * Dc + n;
            *(float2*)&g_partial[o] =
                make_float2(acc[mt][nt][0], acc[mt][nt][1]);
            *(float2*)&g_partial[o + 8 * (size_t)Dc] =
                make_float2(acc[mt][nt][2], acc[mt][nt][3]);
        }
}

// ---------------------------------------------------------------------------
// K2a: reduce split-K partials. grid(64,2), 256 threads.
// ---------------------------------------------------------------------------
__global__ void __launch_bounds__(256)
reduce_kernel() {
    const int b = blockIdx.x;
    const int d = blockIdx.y * 256 + threadIdx.x;
    float v = 0.f;
#pragma unroll 7
    for (int ch = 0; ch < NCH; ch++)
        v += g_partial[((size_t)ch * Bc + b) * Dc + d];
    g_fraw[b * Dc + d] = v;
}

// ---------------------------------------------------------------------------
// K2b: L2-normalize rows. grid(64), 256 threads.
// ---------------------------------------------------------------------------
__global__ void __launch_bounds__(256)
norm_kernel() {
    const int b = blockIdx.x;
    const int t = threadIdx.x;
    float v0 = g_fraw[b * Dc + t];
    float v1 = g_fraw[b * Dc + t + 256];
    __shared__ float red[256];
    red[t] = v0 * v0 + v1 * v1;
    __syncthreads();
    for (int s = 128; s > 0; s >>= 1) {
        if (t < s) red[t] += red[t + s];
        __syncthreads();
    }
    __shared__ float inv;
    if (t == 0) inv = rsqrtf(red[0]);
    __syncthreads();
    g_f[b * Dc + t]       = v0 * inv;
    g_f[b * Dc + t + 256] = v1 * inv;
}

// ---------------------------------------------------------------------------
// K3: index multiplicity cnt[c,d]. grid(100), 512 threads (one per d).
// ---------------------------------------------------------------------------
__global__ void __launch_bounds__(512)
cnt_kernel(const int* __restrict__ indices) {
    __shared__ int idx[NFc];
    const int c = blockIdx.x;
    const int t = threadIdx.x;
    if (t < NFc) idx[t] = indices[c * NFc + t];
    __syncthreads();
    int cnt = 0;
#pragma unroll 16
    for (int f = 0; f < NFc; f++)
        cnt += (idx[f] == t);
    g_cnt[c * Dc + t] = (float)cnt;
}

// ---------------------------------------------------------------------------
// K4: dense key-logit partials.  S[c,m,j] = sum_d cnt[c,d]*keys[c,m,d]*text[j,d]
// grid(100 classes, 4 d-chunks of 128), 256 threads, dyn smem 93184 B.
// Thread tile: 4 m x 7 j (j = tx + 16*q, padded to 112).
// ---------------------------------------------------------------------------
#define SKEY_SMEM ((128 * 68 + 128 * 113 + 128) * 4)

__global__ void __launch_bounds__(256, 2)
skey_kernel(const float* __restrict__ keys, const float* __restrict__ text) {
    extern __shared__ float sm[];
    float* ks = sm;                    // [128 d][68] (64 m used)
    float* ts = sm + 128 * 68;         // [128 d][113] (112 j used)
    float* cw = sm + 128 * 68 + 128 * 113;  // [128]

    const int c  = blockIdx.x;
    const int dc = blockIdx.y;
    const int d0 = dc * 128;
    const int t  = threadIdx.x;

    if (t < 128) cw[t] = g_cnt[c * Dc + d0 + t];
    __syncthreads();

    // keys tile: 64 m x 128 d -> ks[d][m] * cnt
#pragma unroll
    for (int i = 0; i < 8; i++) {
        int idx = i * 256 + t;
        int m = idx >> 5, dq = idx & 31;
        float4 v = *(const float4*)&keys[((size_t)(c * Mc + m)) * Dc + d0 + dq * 4];
        ks[(dq * 4 + 0) * 68 + m] = v.x * cw[dq * 4 + 0];
        ks[(dq * 4 + 1) * 68 + m] = v.y * cw[dq * 4 + 1];
        ks[(dq * 4 + 2) * 68 + m] = v.z * cw[dq * 4 + 2];
        ks[(dq * 4 + 3) * 68 + m] = v.w * cw[dq * 4 + 3];
    }
    // text tile: 112 j x 128 d -> ts[d][j] (zero pad j >= 100)
#pragma unroll
    for (int i = 0; i < 14; i++) {
        int idx = i * 256 + t;
        int j = idx >> 5, dq = idx & 31;
        float4 v = make_float4(0.f, 0.f, 0.f, 0.f);
        if (j < Cc) v = *(const float4*)&text[(size_t)j * Dc + d0 + dq * 4];
        ts[(dq * 4 + 0) * 113 + j] = v.x;
        ts[(dq * 4 + 1) * 113 + j] = v.y;
        ts[(dq * 4 + 2) * 113 + j] = v.z;
        ts[(dq * 4 + 3) * 113 + j] = v.w;
    }
    __syncthreads();

    const int ty = t >> 4;     // m group: m = ty*4 + i
    const int tx = t & 15;     // j group: j = tx + 16*q

    float acc[4][7];
#pragma unroll
    for (int i = 0; i < 4; i++)
#pragma unroll
        for (int q = 0; q < 7; q++) acc[i][q] = 0.f;

#pragma unroll 4
    for (int dd = 0; dd < 128; dd++) {
        float4 kv = *(const float4*)&ks[dd * 68 + ty * 4];
        float tj[7];
#pragma unroll
        for (int q = 0; q < 7; q++) tj[q] = ts[dd * 113 + tx + 16 * q];
#pragma unroll
        for (int q = 0; q < 7; q++) {
            acc[0][q] += kv.x * tj[q];
            acc[1][q] += kv.y * tj[q];
            acc[2][q] += kv.z * tj[q];
            acc[3][q] += kv.w * tj[q];
        }
    }

    float* out = &g_spart[((size_t)(c * 4 + dc) * Mc) * JP];
#pragma unroll
    for (int i = 0; i < 4; i++)
#pragma unroll
        for (int q = 0; q < 7; q++)
            out[(ty * 4 + i) * JP + tx + 16 * q] = acc[i][q];
}

// ---------------------------------------------------------------------------
// K5: softmax over j + weights.  grid(100), 256 threads (4 lanes per m).
// ---------------------------------------------------------------------------
__global__ void __launch_bounds__(256)
softw_kernel(const float* __restrict__ gamma_p) {
    const int c = blockIdx.x;
    const int t = threadIdx.x;
    const int m = t >> 2;
    const int p = t & 3;
    const float* sp = &g_spart[((size_t)(c * 4) * Mc) * JP];
    const int cs = Mc * JP;

    float den = 0.f, num = 0.f;
    for (int jj = 0; jj < 25; jj++) {
        int j = p * 25 + jj;
        float s = sp[m * JP + j] + sp[cs + m * JP + j]
                + sp[2 * cs + m * JP + j] + sp[3 * cs + m * JP + j];
        float e = expf(s);
        den += e;
        if (j == c) num = e;
    }
    den += __shfl_xor_sync(0xffffffffu, den, 1);
    den += __shfl_xor_sync(0xffffffffu, den, 2);
    num += __shfl_xor_sync(0xffffffffu, num, 1);
    num += __shfl_xor_sync(0xffffffffu, num, 2);

    if (p == 0) {
        float pcc = num / den;
        float KL  = log2f((1.f + 1e-6f) / (pcc + 1e-6f));
        g_w[c * Mc + m] = expf(KL * gamma_p[0]);
    }
}

// ---------------------------------------------------------------------------
// K6: kwd[c,d] = cnt[c,d] * sum_m keys[c,m,d]*w[c,m]. grid(100,2), 256 thr.
// ---------------------------------------------------------------------------
__global__ void __launch_bounds__(256)
kwd_kernel(const float* __restrict__ keys) {
    __shared__ float ws[Mc];
    const int c = blockIdx.x;
    const int t = threadIdx.x;
    const int d = blockIdx.y * 256 + t;
    if (t < Mc) ws[t] = g_w[c * Mc + t];
    __syncthreads();

    float s = 0.f;
#pragma unroll 8
    for (int m = 0; m < Mc; m++)
        s += keys[((size_t)(c * Mc + m)) * Dc + d] * ws[m];
    g_kwd[c * Dc + d] = s * g_cnt[c * Dc + d];
}

// ---------------------------------------------------------------------------
// K7: final fused epilogue (dense). grid(100), 256 threads.
// ---------------------------------------------------------------------------
__global__ void __launch_bounds__(256)
final_kernel(const float* __restrict__ text, const float* __restrict__ ls_p,
             const float* __restrict__ alpha_p, const float* __restrict__ beta_p,
             float* __restrict__ out) {
    __shared__ float tc[512];
    __shared__ float kd[512];

    const int c = blockIdx.x;
    const int t = threadIdx.x;

    tc[t]       = text[c * Dc + t];
    tc[t + 256] = text[c * Dc + 256 + t];
    kd[t]       = g_kwd[c * Dc + t];
    kd[t + 256] = g_kwd[c * Dc + 256 + t];
    __syncthreads();

    const int b = t >> 2;
    const int p = t & 3;
    const float* fb = &g_f[b * Dc];

    float clip = 0.f, cache = 0.f;
#pragma unroll 8
    for (int q = 0; q < 32; q++) {
        float4 fv = *(const float4*)&fb[p * 128 + q * 4];
        float4 tv = *(const float4*)&tc[p * 128 + q * 4];
        float4 kv = *(const float4*)&kd[p * 128 + q * 4];
        clip  += fv.x * tv.x + fv.y * tv.y + fv.z * tv.z + fv.w * tv.w;
        cache += fv.x * kv.x + fv.y * kv.y + fv.z * kv.z + fv.w * kv.w;
    }
    clip  += __shfl_xor_sync(0xffffffffu, clip, 1);
    clip  += __shfl_xor_sync(0xffffffffu, clip, 2);
    cache += __shfl_xor_sync(0xffffffffu, cache, 1);
    cache += __shfl_xor_sync(0xffffffffu, cache, 2);

    if (p == 0) {
        float cl = cache * (1.f / (float)Mc);
        float cache_logit = expf(beta_p[0] * cl - beta_p[0]);
        out[b * Cc + c] = alpha_p[0] * cache_logit + expf(ls_p[0]) * clip;
    }
}

// ---------------------------------------------------------------------------
// Launch
// ---------------------------------------------------------------------------
extern "C" void kernel_launch(void* const* d_in, const int* in_sizes, int n_in,
                              void* d_out, int out_size) {
    const float* image   = (const float*)d_in[0];
    const float* W_enc   = (const float*)d_in[1];
    const float* text    = (const float*)d_in[2];
    const float* keys    = (const float*)d_in[3];
    const float* ls      = (const float*)d_in[4];
    const int*   indices = (const int*)d_in[5];
    const float* alpha   = (const float*)d_in[6];
    const float* beta    = (const float*)d_in[7];
    const float* gamma   = (const float*)d_in[8];
    float* out = (float*)d_out;

    cudaFuncSetAttribute(gemm_mma_kernel,
                         cudaFuncAttributeMaxDynamicSharedMemorySize, GEMM_SMEM);
    cudaFuncSetAttribute(skey_kernel,
                         cudaFuncAttributeMaxDynamicSharedMemorySize, SKEY_SMEM);

    gemm_mma_kernel<<<dim3(4, NCH), 256, GEMM_SMEM>>>(image, W_enc);
    reduce_kernel<<<dim3(Bc, 2), 256>>>();
    norm_kernel<<<Bc, 256>>>();
    cnt_kernel<<<Cc, 512>>>(indices);
    skey_kernel<<<dim3(Cc, 4), 256, SKEY_SMEM>>>(keys, text);
    softw_kernel<<<Cc, 256>>>(gamma);
    kwd_kernel<<<dim3(Cc, 2), 256>>>(keys);
    final_kernel<<<Cc, 256>>>(text, ls, alpha, beta, out);
}

// round 7
// speedup vs baseline: 2.4066x; 1.1224x over previous
#include <cuda_runtime.h>
#include <cuda_bf16.h>

typedef unsigned int u32;
typedef unsigned long long u64;

#define Bc   64
#define DINc 150528
#define Dc   512
#define Cc   100
#define Mc   64
#define NFc  256
#define KC   1024
#define NCH  147
#define DT   128
#define JP   112        // padded j extent for S tiles

__device__ float g_partial[NCH * Bc * Dc];   // split-K partials [chunk][b][d]
__device__ float g_fraw[Bc * Dc];
__device__ float g_f[Bc * Dc];
__device__ float g_cnt[Cc * Dc];             // index multiplicity per (c,d)
__device__ float g_spart[Cc * 4 * Mc * JP];  // S partials [c][dchunk][m][j]
__device__ float g_w[Cc * Mc];               // per-key weights
__device__ float g_kwd[Cc * Dc];             // dense kw

// ---------------- helpers ----------------
__device__ __forceinline__ u32 smem_u32(const void* p) {
    u32 a;
    asm("{ .reg .u64 t; cvta.to.shared.u64 t, %1; cvt.u32.u64 %0, t; }" : "=r"(a) : "l"(p));
    return a;
}
__device__ __forceinline__ void cvt_split(float x0, float x1, u32& h, u32& l) {
    asm("cvt.rn.bf16x2.f32 %0, %1, %2;" : "=r"(h) : "f"(x1), "f"(x0));
    float h0 = __int_as_float(h << 16);
    float h1 = __int_as_float(h & 0xFFFF0000u);
    asm("cvt.rn.bf16x2.f32 %0, %1, %2;" : "=r"(l) : "f"(x1 - h1), "f"(x0 - h0));
}
__device__ __forceinline__ void ldmA(u32* r, u32 addr) {
    asm volatile("ldmatrix.sync.aligned.m8n8.x4.shared.b16 {%0,%1,%2,%3}, [%4];"
        : "=r"(r[0]), "=r"(r[1]), "=r"(r[2]), "=r"(r[3]) : "r"(addr));
}
__device__ __forceinline__ void ldmBT(u32* r, u32 addr) {
    asm volatile("ldmatrix.sync.aligned.m8n8.x4.trans.shared.b16 {%0,%1,%2,%3}, [%4];"
        : "=r"(r[0]), "=r"(r[1]), "=r"(r[2]), "=r"(r[3]) : "r"(addr));
}
__device__ __forceinline__ void mma16816(float* c, const u32* a, u32 b0, u32 b1) {
    asm volatile(
        "mma.sync.aligned.m16n8k16.row.col.f32.bf16.bf16.f32 "
        "{%0,%1,%2,%3}, {%4,%5,%6,%7}, {%8,%9}, {%0,%1,%2,%3};"
        : "+f"(c[0]), "+f"(c[1]), "+f"(c[2]), "+f"(c[3])
        : "r"(a[0]), "r"(a[1]), "r"(a[2]), "r"(a[3]), "r"(b0), "r"(b1));
}

// ---------------------------------------------------------------------------
// K1: split-bf16 3-pass HMMA split-K GEMM.  Double-buffered smem, single
// __syncthreads per k-iter, fragment sharing.  grid(4,147), 256 threads.
// ---------------------------------------------------------------------------
#define A_STRIDE 20
#define B_STRIDE 68
#define A_BUF (64 * A_STRIDE)
#define B_BUF (32 * B_STRIDE)
#define GEMM_SMEM ((2 * A_BUF * 2 + 2 * B_BUF * 2) * 4)   // 55296 B

__global__ void __launch_bounds__(256, 2)
gemm_mma_kernel(const float* __restrict__ A, const float* __restrict__ W) {
    extern __shared__ u32 dsm[];
    u32* AsH = dsm;
    u32* AsL = dsm + 2 * A_BUF;
    u32* BsH = dsm + 4 * A_BUF;
    u32* BsL = dsm + 4 * A_BUF + 2 * B_BUF;

    const int t = threadIdx.x, w = t >> 5, l = t & 31;
    const int wm = w >> 2, wn = w & 3;
    const int dt0 = blockIdx.x * DT;
    const size_t kb = (size_t)blockIdx.y * KC;

    const u32 aRowOff = (u32)(wm * 32 + (l & 7) + ((l >> 3) & 1) * 8) * (A_STRIDE * 4)
                        + ((l & 16) ? 16u : 0u);
    const u32 bOff = (u32)((l & 7) + ((l >> 3) & 1) * 8) * (B_STRIDE * 4)
                     + (u32)(wn * 32 + ((l & 16) ? 8 : 0)) * 2;

    const int am = t >> 3, akq = t & 7;
    const int bk = t >> 5, bdq = t & 31;
    const float* Ap = A + (size_t)am * DINc + kb + akq * 4;
    const float* Wp = W + (size_t)(kb + bk) * Dc + dt0 + bdq * 4;

    float acc[2][4][4];
#pragma unroll
    for (int i = 0; i < 2; i++)
#pragma unroll
        for (int j = 0; j < 4; j++)
#pragma unroll
            for (int q = 0; q < 4; q++) acc[i][j][q] = 0.f;

    float4 pfA[2], pfB[4];
#pragma unroll
    for (int i = 0; i < 2; i++) pfA[i] = *(const float4*)(Ap + (size_t)(i * 32) * DINc);
#pragma unroll
    for (int i = 0; i < 4; i++) pfB[i] = *(const float4*)(Wp + (size_t)(i * 8) * Dc);

    for (int k0 = 0; k0 < KC; k0 += 32) {
        const int buf = (k0 >> 5) & 1;
        u32* aH = AsH + buf * A_BUF;
        u32* aL = AsL + buf * A_BUF;
        u32* bH = BsH + buf * B_BUF;
        u32* bL = BsL + buf * B_BUF;

#pragma unroll
        for (int i = 0; i < 2; i++) {
            u32 h0, l0, h1, l1;
            cvt_split(pfA[i].x, pfA[i].y, h0, l0);
            cvt_split(pfA[i].z, pfA[i].w, h1, l1);
            int woff = (i * 32 + am) * A_STRIDE + akq * 2;
            *(u64*)&aH[woff] = ((u64)h1 << 32) | h0;
            *(u64*)&aL[woff] = ((u64)l1 << 32) | l0;
        }
#pragma unroll
        for (int i = 0; i < 4; i++) {
            u32 h0, l0, h1, l1;
            cvt_split(pfB[i].x, pfB[i].y, h0, l0);
            cvt_split(pfB[i].z, pfB[i].w, h1, l1);
            int woff = (i * 8 + bk) * B_STRIDE + bdq * 2;
            *(u64*)&bH[woff] = ((u64)h1 << 32) | h0;
            *(u64*)&bL[woff] = ((u64)l1 << 32) | l0;
        }
        if (k0 + 32 < KC) {
#pragma unroll
            for (int i = 0; i < 2; i++)
                pfA[i] = *(const float4*)(Ap + (size_t)(i * 32) * DINc + k0 + 32);
#pragma unroll
            for (int i = 0; i < 4; i++)
                pfB[i] = *(const float4*)(Wp + (size_t)(i * 8 + k0 + 32) * Dc);
        }
        __syncthreads();

        const u32 aHb = smem_u32(aH), aLb = smem_u32(aL);
        const u32 bHb = smem_u32(bH), bLb = smem_u32(bL);
#pragma unroll
        for (int ks = 0; ks < 2; ks++) {
            u32 fAH[2][4], fAL[2][4];
            ldmA(fAH[0], aHb + aRowOff + ks * 32);
            ldmA(fAH[1], aHb + aRowOff + 16 * (A_STRIDE * 4) + ks * 32);
            ldmA(fAL[0], aLb + aRowOff + ks * 32);
            ldmA(fAL[1], aLb + aRowOff + 16 * (A_STRIDE * 4) + ks * 32);
#pragma unroll
            for (int j = 0; j < 2; j++) {
                u32 fBH[4], fBL[4];
                ldmBT(fBH, bHb + bOff + ks * 16 * (B_STRIDE * 4) + j * 32);
                ldmBT(fBL, bLb + bOff + ks * 16 * (B_STRIDE * 4) + j * 32);
#pragma unroll
                for (int mt = 0; mt < 2; mt++) {
                    mma16816(acc[mt][2 * j],     fAH[mt], fBH[0], fBH[1]);
                    mma16816(acc[mt][2 * j + 1], fAH[mt], fBH[2], fBH[3]);
                    mma16816(acc[mt][2 * j],     fAH[mt], fBL[0], fBL[1]);
                    mma16816(acc[mt][2 * j + 1], fAH[mt], fBL[2], fBL[3]);
                    mma16816(acc[mt][2 * j],     fAL[mt], fBH[0], fBH[1]);
                    mma16816(acc[mt][2 * j + 1], fAL[mt], fBH[2], fBH[3]);
                }
            }
        }
    }

    const int g = l >> 2, t4 = l & 3;
#pragma unroll
    for (int mt = 0; mt < 2; mt++)
#pragma unroll
        for (int nt = 0; nt < 4; nt++) {
            int m = wm * 32 + mt * 16 + g;
            int n = dt0 + wn * 32 + nt * 8 + t4 * 2;
            size_t o = ((size_t)(blockIdx.y * 64 + m)) * Dc + n;
            *(float2*)&g_partial[o] =
                make_float2(acc[mt][nt][0], acc[mt][nt][1]);
            *(float2*)&g_partial[o + 8 * (size_t)Dc] =
                make_float2(acc[mt][nt][2], acc[mt][nt][3]);
        }
}

// ---------------------------------------------------------------------------
// K2a: reduce split-K partials. grid(64,2), 256 threads.
// ---------------------------------------------------------------------------
__global__ void __launch_bounds__(256)
reduce_kernel() {
    const int b = blockIdx.x;
    const int d = blockIdx.y * 256 + threadIdx.x;
    float v = 0.f;
#pragma unroll 7
    for (int ch = 0; ch < NCH; ch++)
        v += g_partial[((size_t)ch * Bc + b) * Dc + d];
    g_fraw[b * Dc + d] = v;
}

// ---------------------------------------------------------------------------
// K2b: L2-normalize rows. grid(64), 256 threads.
// ---------------------------------------------------------------------------
__global__ void __launch_bounds__(256)
norm_kernel() {
    const int b = blockIdx.x;
    const int t = threadIdx.x;
    float v0 = g_fraw[b * Dc + t];
    float v1 = g_fraw[b * Dc + t + 256];
    __shared__ float red[256];
    red[t] = v0 * v0 + v1 * v1;
    __syncthreads();
    for (int s = 128; s > 0; s >>= 1) {
        if (t < s) red[t] += red[t + s];
        __syncthreads();
    }
    __shared__ float inv;
    if (t == 0) inv = rsqrtf(red[0]);
    __syncthreads();
    g_f[b * Dc + t]       = v0 * inv;
    g_f[b * Dc + t + 256] = v1 * inv;
}

// ---------------------------------------------------------------------------
// K3: index multiplicity via shared histogram (integer atomics, order-
// invariant -> deterministic). grid(100), 256 threads.
// ---------------------------------------------------------------------------
__global__ void __launch_bounds__(256)
cnt_kernel(const int* __restrict__ indices) {
    __shared__ int h[Dc];
    const int c = blockIdx.x;
    const int t = threadIdx.x;
    h[t] = 0;
    h[t + 256] = 0;
    __syncthreads();
    atomicAdd(&h[indices[c * NFc + t]], 1);
    __syncthreads();
    g_cnt[c * Dc + t]       = (float)h[t];
    g_cnt[c * Dc + t + 256] = (float)h[t + 256];
}

// ---------------------------------------------------------------------------
// K4: dense key-logit partials.  S[c,m,j] = sum_d cnt[c,d]*keys[c,m,d]*text[j,d]
// grid(100, 4 d-chunks), 256 threads, dyn smem 93184 B.
// ---------------------------------------------------------------------------
#define SKEY_SMEM ((128 * 68 + 128 * 113 + 128) * 4)

__global__ void __launch_bounds__(256, 2)
skey_kernel(const float* __restrict__ keys, const float* __restrict__ text) {
    extern __shared__ float sm[];
    float* ks = sm;                    // [128 d][68] (64 m used)
    float* ts = sm + 128 * 68;         // [128 d][113] (112 j used)
    float* cw = sm + 128 * 68 + 128 * 113;  // [128]

    const int c  = blockIdx.x;
    const int dc = blockIdx.y;
    const int d0 = dc * 128;
    const int t  = threadIdx.x;

    if (t < 128) cw[t] = g_cnt[c * Dc + d0 + t];
    __syncthreads();

#pragma unroll
    for (int i = 0; i < 8; i++) {
        int idx = i * 256 + t;
        int m = idx >> 5, dq = idx & 31;
        float4 v = *(const float4*)&keys[((size_t)(c * Mc + m)) * Dc + d0 + dq * 4];
        ks[(dq * 4 + 0) * 68 + m] = v.x * cw[dq * 4 + 0];
        ks[(dq * 4 + 1) * 68 + m] = v.y * cw[dq * 4 + 1];
        ks[(dq * 4 + 2) * 68 + m] = v.z * cw[dq * 4 + 2];
        ks[(dq * 4 + 3) * 68 + m] = v.w * cw[dq * 4 + 3];
    }
#pragma unroll
    for (int i = 0; i < 14; i++) {
        int idx = i * 256 + t;
        int j = idx >> 5, dq = idx & 31;
        float4 v = make_float4(0.f, 0.f, 0.f, 0.f);
        if (j < Cc) v = *(const float4*)&text[(size_t)j * Dc + d0 + dq * 4];
        ts[(dq * 4 + 0) * 113 + j] = v.x;
        ts[(dq * 4 + 1) * 113 + j] = v.y;
        ts[(dq * 4 + 2) * 113 + j] = v.z;
        ts[(dq * 4 + 3) * 113 + j] = v.w;
    }
    __syncthreads();

    const int ty = t >> 4;
    const int tx = t & 15;

    float acc[4][7];
#pragma unroll
    for (int i = 0; i < 4; i++)
#pragma unroll
        for (int q = 0; q < 7; q++) acc[i][q] = 0.f;

#pragma unroll 4
    for (int dd = 0; dd < 128; dd++) {
        float4 kv = *(const float4*)&ks[dd * 68 + ty * 4];
        float tj[7];
#pragma unroll
        for (int q = 0; q < 7; q++) tj[q] = ts[dd * 113 + tx + 16 * q];
#pragma unroll
        for (int q = 0; q < 7; q++) {
            acc[0][q] += kv.x * tj[q];
            acc[1][q] += kv.y * tj[q];
            acc[2][q] += kv.z * tj[q];
            acc[3][q] += kv.w * tj[q];
        }
    }

    float* out = &g_spart[((size_t)(c * 4 + dc) * Mc) * JP];
#pragma unroll
    for (int i = 0; i < 4; i++)
#pragma unroll
        for (int q = 0; q < 7; q++)
            out[(ty * 4 + i) * JP + tx + 16 * q] = acc[i][q];
}

// ---------------------------------------------------------------------------
// K5: softmax over j + weights.  grid(100), 256 threads.
// ---------------------------------------------------------------------------
__global__ void __launch_bounds__(256)
softw_kernel(const float* __restrict__ gamma_p) {
    const int c = blockIdx.x;
    const int t = threadIdx.x;
    const int m = t >> 2;
    const int p = t & 3;
    const float* sp = &g_spart[((size_t)(c * 4) * Mc) * JP];
    const int cs = Mc * JP;

    float den = 0.f, num = 0.f;
    for (int jj = 0; jj < 25; jj++) {
        int j = p * 25 + jj;
        float s = sp[m * JP + j] + sp[cs + m * JP + j]
                + sp[2 * cs + m * JP + j] + sp[3 * cs + m * JP + j];
        float e = expf(s);
        den += e;
        if (j == c) num = e;
    }
    den += __shfl_xor_sync(0xffffffffu, den, 1);
    den += __shfl_xor_sync(0xffffffffu, den, 2);
    num += __shfl_xor_sync(0xffffffffu, num, 1);
    num += __shfl_xor_sync(0xffffffffu, num, 2);

    if (p == 0) {
        float pcc = num / den;
        float KL  = log2f((1.f + 1e-6f) / (pcc + 1e-6f));
        g_w[c * Mc + m] = expf(KL * gamma_p[0]);
    }
}

// ---------------------------------------------------------------------------
// K6: kwd[c,d] = cnt[c,d] * sum_m keys[c,m,d]*w[c,m]. grid(100,2), 256 thr.
// ---------------------------------------------------------------------------
__global__ void __launch_bounds__(256)
kwd_kernel(const float* __restrict__ keys) {
    __shared__ float ws[Mc];
    const int c = blockIdx.x;
    const int t = threadIdx.x;
    const int d = blockIdx.y * 256 + t;
    if (t < Mc) ws[t] = g_w[c * Mc + t];
    __syncthreads();

    float s = 0.f;
#pragma unroll 8
    for (int m = 0; m < Mc; m++)
        s += keys[((size_t)(c * Mc + m)) * Dc + d] * ws[m];
    g_kwd[c * Dc + d] = s * g_cnt[c * Dc + d];
}

// ---------------------------------------------------------------------------
// K7: final fused epilogue (dense). grid(100), 256 threads.
// ---------------------------------------------------------------------------
__global__ void __launch_bounds__(256)
final_kernel(const float* __restrict__ text, const float* __restrict__ ls_p,
             const float* __restrict__ alpha_p, const float* __restrict__ beta_p,
             float* __restrict__ out) {
    __shared__ float tc[512];
    __shared__ float kd[512];

    const int c = blockIdx.x;
    const int t = threadIdx.x;

    tc[t]       = text[c * Dc + t];
    tc[t + 256] = text[c * Dc + 256 + t];
    kd[t]       = g_kwd[c * Dc + t];
    kd[t + 256] = g_kwd[c * Dc + 256 + t];
    __syncthreads();

    const int b = t >> 2;
    const int p = t & 3;
    const float* fb = &g_f[b * Dc];

    float clip = 0.f, cache = 0.f;
#pragma unroll 8
    for (int q = 0; q < 32; q++) {
        float4 fv = *(const float4*)&fb[p * 128 + q * 4];
        float4 tv = *(const float4*)&tc[p * 128 + q * 4];
        float4 kv = *(const float4*)&kd[p * 128 + q * 4];
        clip  += fv.x * tv.x + fv.y * tv.y + fv.z * tv.z + fv.w * tv.w;
        cache += fv.x * kv.x + fv.y * kv.y + fv.z * kv.z + fv.w * kv.w;
    }
    clip  += __shfl_xor_sync(0xffffffffu, clip, 1);
    clip  += __shfl_xor_sync(0xffffffffu, clip, 2);
    cache += __shfl_xor_sync(0xffffffffu, cache, 1);
    cache += __shfl_xor_sync(0xffffffffu, cache, 2);

    if (p == 0) {
        float cl = cache * (1.f / (float)Mc);
        float cache_logit = expf(beta_p[0] * cl - beta_p[0]);
        out[b * Cc + c] = alpha_p[0] * cache_logit + expf(ls_p[0]) * clip;
    }
}

// ---------------------------------------------------------------------------
// Launch: fork key chain onto a second stream so it overlaps the GEMM chain.
// Stream/events created lazily on the (uncaptured) correctness call; the
// event fork/join pattern is capture-legal and yields a parallel graph.
// ---------------------------------------------------------------------------
extern "C" void kernel_launch(void* const* d_in, const int* in_sizes, int n_in,
                              void* d_out, int out_size) {
    const float* image   = (const float*)d_in[0];
    const float* W_enc   = (const float*)d_in[1];
    const float* text    = (const float*)d_in[2];
    const float* keys    = (const float*)d_in[3];
    const float* ls      = (const float*)d_in[4];
    const int*   indices = (const int*)d_in[5];
    const float* alpha   = (const float*)d_in[6];
    const float* beta    = (const float*)d_in[7];
    const float* gamma   = (const float*)d_in[8];
    float* out = (float*)d_out;

    static cudaStream_t s2 = nullptr;
    static cudaEvent_t evFork = nullptr, evJoin = nullptr;
    if (s2 == nullptr) {
        cudaStreamCreateWithFlags(&s2, cudaStreamNonBlocking);
        cudaEventCreateWithFlags(&evFork, cudaEventDisableTiming);
        cudaEventCreateWithFlags(&evJoin, cudaEventDisableTiming);
        cudaFuncSetAttribute(gemm_mma_kernel,
                             cudaFuncAttributeMaxDynamicSharedMemorySize, GEMM_SMEM);
        cudaFuncSetAttribute(skey_kernel,
                             cudaFuncAttributeMaxDynamicSharedMemorySize, SKEY_SMEM);
    }

    // fork
    cudaEventRecord(evFork, 0);
    cudaStreamWaitEvent(s2, evFork, 0);

    // branch A (stream 0): features
    gemm_mma_kernel<<<dim3(4, NCH), 256, GEMM_SMEM>>>(image, W_enc);
    reduce_kernel<<<dim3(Bc, 2), 256>>>();
    norm_kernel<<<Bc, 256>>>();

    // branch B (s2): key weights
    cnt_kernel<<<Cc, 256, 0, s2>>>(indices);
    skey_kernel<<<dim3(Cc, 4), 256, SKEY_SMEM, s2>>>(keys, text);
    softw_kernel<<<Cc, 256, 0, s2>>>(gamma);
    kwd_kernel<<<dim3(Cc, 2), 256, 0, s2>>>(keys);

    // join
    cudaEventRecord(evJoin, s2);
    cudaStreamWaitEvent(0, evJoin, 0);

    final_kernel<<<Cc, 256>>>(text, ls, alpha, beta, out);
}